// round 4
// baseline (speedup 1.0000x reference)
#include <cuda_runtime.h>
#include <cuda_bf16.h>
#include <cstdint>

#define Nn 100000
#define Ee 3200000
#define Bb 64
#define FIN 64
#define EIN 16
#define ADIM 13
#define Hh 32
#define OUT 64
#define EPS_GEN 1e-7f
#define EPS_BN 1e-5f

#define SCAN_B 1024
#define NSCAN ((Nn + SCAN_B - 1) / SCAN_B)   // 98

// ---------------- scratch (device globals; no allocs allowed) ----------------
__device__ float  g_h[Nn * Hh];        // node encoder output [N,32]
__device__ float  g_z[Nn * Hh];        // agg + h (GENConv output pre-MLP)
__device__ float  g_y1[Nn * OUT];
__device__ float  g_y2[Nn * OUT];
__device__ float  g_y3[Nn * OUT];
__device__ double g_stats[3 * 128];    // per stage: [sum(64) | sumsq(64)]
__device__ float  g_pool[Bb * OUT];
__device__ float  g_cnt[Bb];
// sort-by-dst scratch
__device__ int    g_deg[Nn];
__device__ int    g_off[Nn + 1];
__device__ int    g_cur[Nn];
__device__ int    g_part[NSCAN];
__device__ int    g_partoff[NSCAN];
__device__ int2   g_epack[Ee];         // (edge id, src) in dst-sorted order

// ---------------- helpers ----------------
__device__ __forceinline__ void red_add_v4(float* addr, float4 v) {
    asm volatile("red.global.add.v4.f32 [%0], {%1,%2,%3,%4};"
                 :: "l"(addr), "f"(v.x), "f"(v.y), "f"(v.z), "f"(v.w) : "memory");
}

__device__ __forceinline__ void fma_row(float4& acc, float zv, float4 wv) {
    acc.x = fmaf(zv, wv.x, acc.x);
    acc.y = fmaf(zv, wv.y, acc.y);
    acc.z = fmaf(zv, wv.z, acc.z);
    acc.w = fmaf(zv, wv.w, acc.w);
}

// ---------------- 0: zero scratch ----------------
__global__ void zero_kernel() {
    int idx = blockIdx.x * blockDim.x + threadIdx.x;
    int stride = gridDim.x * blockDim.x;
    for (int i = idx; i < Nn; i += stride) g_deg[i] = 0;
    for (int i = idx; i < Bb * OUT; i += stride) g_pool[i] = 0.f;
    for (int i = idx; i < Bb; i += stride) g_cnt[i] = 0.f;
    for (int i = idx; i < 3 * 128; i += stride) g_stats[i] = 0.0;
}

// ---------------- 1: node encoder  h = x @ node_w + node_b  [N,64]->[N,32] ----
__global__ void __launch_bounds__(128) enc_kernel(const float* __restrict__ x,
                                                  const float* __restrict__ W,
                                                  const float* __restrict__ bias) {
    __shared__ __align__(16) float zs[64 * 68];
    __shared__ __align__(16) float ws[FIN * Hh];   // 64x32
    int tid = threadIdx.x;
    int n0 = blockIdx.x * 64;
    for (int i = tid; i < FIN * Hh; i += 128) ws[i] = W[i];
    for (int i = tid; i < 64 * FIN; i += 128) {
        int n = i >> 6, k = i & 63;
        int gn = n0 + n;
        zs[n * 68 + k] = (gn < Nn) ? x[(size_t)gn * FIN + k] : 0.f;
    }
    __syncthreads();
    int ti = tid >> 3, tj = tid & 7;           // 16 x 8
    float4 acc0 = {0,0,0,0}, acc1 = {0,0,0,0}, acc2 = {0,0,0,0}, acc3 = {0,0,0,0};
    const float4* ws4 = reinterpret_cast<const float4*>(ws); // [k][8]
    #pragma unroll
    for (int k4 = 0; k4 < 16; k4++) {
        float4 z0 = *reinterpret_cast<const float4*>(zs + (4*ti+0)*68 + 4*k4);
        float4 z1 = *reinterpret_cast<const float4*>(zs + (4*ti+1)*68 + 4*k4);
        float4 z2 = *reinterpret_cast<const float4*>(zs + (4*ti+2)*68 + 4*k4);
        float4 z3 = *reinterpret_cast<const float4*>(zs + (4*ti+3)*68 + 4*k4);
        float4 w0 = ws4[(4*k4+0)*8 + tj];
        float4 w1 = ws4[(4*k4+1)*8 + tj];
        float4 w2 = ws4[(4*k4+2)*8 + tj];
        float4 w3 = ws4[(4*k4+3)*8 + tj];
        fma_row(acc0, z0.x, w0); fma_row(acc0, z0.y, w1); fma_row(acc0, z0.z, w2); fma_row(acc0, z0.w, w3);
        fma_row(acc1, z1.x, w0); fma_row(acc1, z1.y, w1); fma_row(acc1, z1.z, w2); fma_row(acc1, z1.w, w3);
        fma_row(acc2, z2.x, w0); fma_row(acc2, z2.y, w1); fma_row(acc2, z2.z, w2); fma_row(acc2, z2.w, w3);
        fma_row(acc3, z3.x, w0); fma_row(acc3, z3.y, w1); fma_row(acc3, z3.z, w2); fma_row(acc3, z3.w, w3);
    }
    float4 bb = *reinterpret_cast<const float4*>(bias + 4*tj);
    float4 accs[4] = {acc0, acc1, acc2, acc3};
    #pragma unroll
    for (int r = 0; r < 4; r++) {
        int gn = n0 + 4*ti + r;
        if (gn < Nn) {
            float4 v = accs[r];
            v.x += bb.x; v.y += bb.y; v.z += bb.z; v.w += bb.w;
            *reinterpret_cast<float4*>(g_h + (size_t)gn * Hh + 4*tj) = v;
        }
    }
}

// ---------------- 2a: histogram of dst --------------------------------------
__global__ void hist_kernel(const int* __restrict__ ei) {
    int idx = blockIdx.x * blockDim.x + threadIdx.x;
    int stride = gridDim.x * blockDim.x;
    for (int e = idx; e < Ee; e += stride)
        atomicAdd(&g_deg[ei[Ee + e]], 1);
}

// ---------------- 2b: scan step 1: per-block partial sums --------------------
__global__ void __launch_bounds__(SCAN_B) scan1_kernel() {
    __shared__ int sred[32];
    int t = threadIdx.x;
    int i = blockIdx.x * SCAN_B + t;
    int v = (i < Nn) ? g_deg[i] : 0;
    #pragma unroll
    for (int o = 16; o; o >>= 1) v += __shfl_down_sync(0xffffffffu, v, o);
    int warp = t >> 5, lane = t & 31;
    if (lane == 0) sred[warp] = v;
    __syncthreads();
    if (warp == 0) {
        v = sred[lane];
        #pragma unroll
        for (int o = 16; o; o >>= 1) v += __shfl_down_sync(0xffffffffu, v, o);
        if (lane == 0) g_part[blockIdx.x] = v;
    }
}

// ---------------- 2c: scan step 2: scan block partials (1 block) --------------
__global__ void __launch_bounds__(128) scan2_kernel() {
    __shared__ int s[128];
    int t = threadIdx.x;
    int v = (t < NSCAN) ? g_part[t] : 0;
    s[t] = v;
    __syncthreads();
    #pragma unroll
    for (int o = 1; o < 128; o <<= 1) {
        int add = (t >= o) ? s[t - o] : 0;
        __syncthreads();
        s[t] += add;
        __syncthreads();
    }
    if (t < NSCAN) g_partoff[t] = s[t] - v;   // exclusive
    if (t == 0) g_off[Nn] = Ee;
}

// ---------------- 2d: scan step 3: per-block exclusive scan + add ------------
__global__ void __launch_bounds__(SCAN_B) scan3_kernel() {
    __shared__ int s[SCAN_B];
    int t = threadIdx.x;
    int i = blockIdx.x * SCAN_B + t;
    int v = (i < Nn) ? g_deg[i] : 0;
    s[t] = v;
    __syncthreads();
    #pragma unroll
    for (int o = 1; o < SCAN_B; o <<= 1) {
        int add = (t >= o) ? s[t - o] : 0;
        __syncthreads();
        s[t] += add;
        __syncthreads();
    }
    if (i < Nn) {
        int excl = s[t] - v + g_partoff[blockIdx.x];
        g_off[i] = excl;
        g_cur[i] = excl;
    }
}

// ---------------- 2e: scatter edges into dst-sorted order --------------------
__global__ void scatter_kernel(const int* __restrict__ ei) {
    int idx = blockIdx.x * blockDim.x + threadIdx.x;
    int stride = gridDim.x * blockDim.x;
    for (int e = idx; e < Ee; e += stride) {
        int dst = ei[Ee + e];
        int src = ei[e];
        int slot = atomicAdd(&g_cur[dst], 1);
        g_epack[slot] = make_int2(e, src);
    }
}

// ---------------- 2f: warp-per-node aggregation ------------------------------
// lane = feature j (Hh == 32). z[n] = softmax-agg + h[n], no atomics.
__global__ void __launch_bounds__(256) agg_kernel(const float* __restrict__ eattr,
                                                  const float* __restrict__ ew,
                                                  const float* __restrict__ eb) {
    int warp_id = (blockIdx.x * blockDim.x + threadIdx.x) >> 5;
    int lane = threadIdx.x & 31;
    if (warp_id >= Nn) return;
    int n = warp_id;
    float wcol[EIN];
    #pragma unroll
    for (int k = 0; k < EIN; k++) wcol[k] = ew[k * Hh + lane];
    float biasj = eb[lane];
    int start = g_off[n], end = g_off[n + 1];
    float acc_e = 0.f, acc_w = 0.f;
    for (int base = start; base < end; base += 32) {
        int cnt = min(32, end - base);
        int eid = 0, esrc = 0;
        if (lane < cnt) {
            int2 pk = g_epack[base + lane];
            eid = pk.x; esrc = pk.y;
        }
        for (int i = 0; i < cnt; i += 2) {
            int sub = lane >> 4;                 // 0: edge i, 1: edge i+1
            int ii = i + sub;
            int esel = __shfl_sync(0xffffffffu, eid, min(ii, cnt - 1));
            float aval = 0.f;
            if (ii < cnt) aval = eattr[(size_t)esel * EIN + (lane & 15)];
            // ---- edge i ----
            {
                float ea = biasj;
                #pragma unroll
                for (int k = 0; k < EIN; k++)
                    ea = fmaf(__shfl_sync(0xffffffffu, aval, k), wcol[k], ea);
                int s = __shfl_sync(0xffffffffu, esrc, i);
                float hj = g_h[(size_t)s * Hh + lane];
                float m = fmaxf(hj + ea, 0.f) + EPS_GEN;
                float p = __expf(m);
                acc_e += p;
                acc_w += m * p;
            }
            // ---- edge i+1 ----
            if (i + 1 < cnt) {
                float ea = biasj;
                #pragma unroll
                for (int k = 0; k < EIN; k++)
                    ea = fmaf(__shfl_sync(0xffffffffu, aval, 16 + k), wcol[k], ea);
                int s = __shfl_sync(0xffffffffu, esrc, i + 1);
                float hj = g_h[(size_t)s * Hh + lane];
                float m = fmaxf(hj + ea, 0.f) + EPS_GEN;
                float p = __expf(m);
                acc_e += p;
                acc_w += m * p;
            }
        }
    }
    float hself = g_h[(size_t)n * Hh + lane];
    float agg = (acc_e > 0.f) ? acc_w / acc_e : 0.f;
    g_z[(size_t)n * Hh + lane] = agg + hself;
}

// ---------------- 3: stage A  y1 = z@W1+b1 ; stats1 ---------------------------
__global__ void __launch_bounds__(256) stageA_kernel(const float* __restrict__ W,
                                                     const float* __restrict__ bias) {
    __shared__ __align__(16) float zs[64 * 36];
    __shared__ __align__(16) float ws[Hh * OUT];   // 32x64
    __shared__ float ssum[64], ssq[64];
    int tid = threadIdx.x;
    int n0 = blockIdx.x * 64;
    for (int i = tid; i < Hh * OUT; i += 256) ws[i] = W[i];
    if (tid < 64) { ssum[tid] = 0.f; ssq[tid] = 0.f; }
    for (int i = tid; i < 64 * Hh; i += 256) {
        int n = i >> 5, k = i & 31;
        int gn = n0 + n;
        zs[n * 36 + k] = (gn < Nn) ? g_z[(size_t)gn * Hh + k] : 0.f;
    }
    __syncthreads();
    int ti = tid >> 4, tj = tid & 15;
    float4 acc0 = {0,0,0,0}, acc1 = {0,0,0,0}, acc2 = {0,0,0,0}, acc3 = {0,0,0,0};
    const float4* ws4 = reinterpret_cast<const float4*>(ws); // [k][16]
    #pragma unroll
    for (int k4 = 0; k4 < 8; k4++) {
        float4 z0 = *reinterpret_cast<const float4*>(zs + (4*ti+0)*36 + 4*k4);
        float4 z1 = *reinterpret_cast<const float4*>(zs + (4*ti+1)*36 + 4*k4);
        float4 z2 = *reinterpret_cast<const float4*>(zs + (4*ti+2)*36 + 4*k4);
        float4 z3 = *reinterpret_cast<const float4*>(zs + (4*ti+3)*36 + 4*k4);
        float4 w0 = ws4[(4*k4+0)*16 + tj];
        float4 w1 = ws4[(4*k4+1)*16 + tj];
        float4 w2 = ws4[(4*k4+2)*16 + tj];
        float4 w3 = ws4[(4*k4+3)*16 + tj];
        fma_row(acc0, z0.x, w0); fma_row(acc0, z0.y, w1); fma_row(acc0, z0.z, w2); fma_row(acc0, z0.w, w3);
        fma_row(acc1, z1.x, w0); fma_row(acc1, z1.y, w1); fma_row(acc1, z1.z, w2); fma_row(acc1, z1.w, w3);
        fma_row(acc2, z2.x, w0); fma_row(acc2, z2.y, w1); fma_row(acc2, z2.z, w2); fma_row(acc2, z2.w, w3);
        fma_row(acc3, z3.x, w0); fma_row(acc3, z3.y, w1); fma_row(acc3, z3.z, w2); fma_row(acc3, z3.w, w3);
    }
    float4 bb = *reinterpret_cast<const float4*>(bias + 4*tj);
    float4 accs[4] = {acc0, acc1, acc2, acc3};
    float4 ls = {0,0,0,0}, lq = {0,0,0,0};
    #pragma unroll
    for (int r = 0; r < 4; r++) {
        int gn = n0 + 4*ti + r;
        if (gn < Nn) {
            float4 v = accs[r];
            v.x += bb.x; v.y += bb.y; v.z += bb.z; v.w += bb.w;
            *reinterpret_cast<float4*>(g_y1 + (size_t)gn * OUT + 4*tj) = v;
            ls.x += v.x; ls.y += v.y; ls.z += v.z; ls.w += v.w;
            lq.x += v.x*v.x; lq.y += v.y*v.y; lq.z += v.z*v.z; lq.w += v.w*v.w;
        }
    }
    atomicAdd(&ssum[4*tj+0], ls.x); atomicAdd(&ssum[4*tj+1], ls.y);
    atomicAdd(&ssum[4*tj+2], ls.z); atomicAdd(&ssum[4*tj+3], ls.w);
    atomicAdd(&ssq[4*tj+0], lq.x);  atomicAdd(&ssq[4*tj+1], lq.y);
    atomicAdd(&ssq[4*tj+2], lq.z);  atomicAdd(&ssq[4*tj+3], lq.w);
    __syncthreads();
    if (tid < 64) {
        atomicAdd(&g_stats[tid],      (double)ssum[tid]);
        atomicAdd(&g_stats[64 + tid], (double)ssq[tid]);
    }
}

// ---------------- 4: stages B/C  z=relu(bn(in)) ; out=z@W+b ; stats ------------
__global__ void __launch_bounds__(256) stageBC_kernel(const float* __restrict__ W,
                                                      const float* __restrict__ bias,
                                                      const float* __restrict__ gam,
                                                      const float* __restrict__ bet,
                                                      int sel) {
    __shared__ __align__(16) float zs[64 * 68];
    __shared__ __align__(16) float ws[OUT * OUT];  // 64x64
    __shared__ float ssum[64], ssq[64], sscale[64], sshift[64];
    const float* in  = sel ? g_y2 : g_y1;
    float*       out = sel ? g_y3 : g_y2;
    int sin  = sel ? 128 : 0;
    int sout = sel ? 256 : 128;
    int tid = threadIdx.x;
    int n0 = blockIdx.x * 64;
    for (int i = tid; i < OUT * OUT; i += 256) ws[i] = W[i];
    if (tid < 64) {
        double mean = g_stats[sin + tid] / (double)Nn;
        double msq  = g_stats[sin + 64 + tid] / (double)Nn;
        double var  = msq - mean * mean;
        float sc = gam[tid] * rsqrtf((float)var + EPS_BN);
        sscale[tid] = sc;
        sshift[tid] = bet[tid] - (float)mean * sc;
        ssum[tid] = 0.f; ssq[tid] = 0.f;
    }
    __syncthreads();
    for (int i = tid; i < 64 * OUT; i += 256) {
        int n = i >> 6, k = i & 63;
        int gn = n0 + n;
        float z = 0.f;
        if (gn < Nn) z = fmaxf(sscale[k] * in[(size_t)gn * OUT + k] + sshift[k], 0.f);
        zs[n * 68 + k] = z;
    }
    __syncthreads();
    int ti = tid >> 4, tj = tid & 15;
    float4 acc0 = {0,0,0,0}, acc1 = {0,0,0,0}, acc2 = {0,0,0,0}, acc3 = {0,0,0,0};
    const float4* ws4 = reinterpret_cast<const float4*>(ws);
    #pragma unroll
    for (int k4 = 0; k4 < 16; k4++) {
        float4 z0 = *reinterpret_cast<const float4*>(zs + (4*ti+0)*68 + 4*k4);
        float4 z1 = *reinterpret_cast<const float4*>(zs + (4*ti+1)*68 + 4*k4);
        float4 z2 = *reinterpret_cast<const float4*>(zs + (4*ti+2)*68 + 4*k4);
        float4 z3 = *reinterpret_cast<const float4*>(zs + (4*ti+3)*68 + 4*k4);
        float4 w0 = ws4[(4*k4+0)*16 + tj];
        float4 w1 = ws4[(4*k4+1)*16 + tj];
        float4 w2 = ws4[(4*k4+2)*16 + tj];
        float4 w3 = ws4[(4*k4+3)*16 + tj];
        fma_row(acc0, z0.x, w0); fma_row(acc0, z0.y, w1); fma_row(acc0, z0.z, w2); fma_row(acc0, z0.w, w3);
        fma_row(acc1, z1.x, w0); fma_row(acc1, z1.y, w1); fma_row(acc1, z1.z, w2); fma_row(acc1, z1.w, w3);
        fma_row(acc2, z2.x, w0); fma_row(acc2, z2.y, w1); fma_row(acc2, z2.z, w2); fma_row(acc2, z2.w, w3);
        fma_row(acc3, z3.x, w0); fma_row(acc3, z3.y, w1); fma_row(acc3, z3.z, w2); fma_row(acc3, z3.w, w3);
    }
    float4 bb = *reinterpret_cast<const float4*>(bias + 4*tj);
    float4 accs[4] = {acc0, acc1, acc2, acc3};
    float4 ls = {0,0,0,0}, lq = {0,0,0,0};
    #pragma unroll
    for (int r = 0; r < 4; r++) {
        int gn = n0 + 4*ti + r;
        if (gn < Nn) {
            float4 v = accs[r];
            v.x += bb.x; v.y += bb.y; v.z += bb.z; v.w += bb.w;
            *reinterpret_cast<float4*>(out + (size_t)gn * OUT + 4*tj) = v;
            ls.x += v.x; ls.y += v.y; ls.z += v.z; ls.w += v.w;
            lq.x += v.x*v.x; lq.y += v.y*v.y; lq.z += v.z*v.z; lq.w += v.w*v.w;
        }
    }
    atomicAdd(&ssum[4*tj+0], ls.x); atomicAdd(&ssum[4*tj+1], ls.y);
    atomicAdd(&ssum[4*tj+2], ls.z); atomicAdd(&ssum[4*tj+3], ls.w);
    atomicAdd(&ssq[4*tj+0], lq.x);  atomicAdd(&ssq[4*tj+1], lq.y);
    atomicAdd(&ssq[4*tj+2], lq.z);  atomicAdd(&ssq[4*tj+3], lq.w);
    __syncthreads();
    if (tid < 64) {
        atomicAdd(&g_stats[sout + tid],      (double)ssum[tid]);
        atomicAdd(&g_stats[sout + 64 + tid], (double)ssq[tid]);
    }
}

// ---------------- 5: stage D  node_out = relu(bn3(y3))@W4+b4, pooled -----------
__global__ void __launch_bounds__(256) stageD_kernel(const float* __restrict__ W,
                                                     const float* __restrict__ bias,
                                                     const float* __restrict__ gam,
                                                     const float* __restrict__ bet,
                                                     const int* __restrict__ batch) {
    __shared__ __align__(16) float zs[64 * 68];
    __shared__ __align__(16) float ws[OUT * OUT];
    __shared__ float sscale[64], sshift[64];
    int tid = threadIdx.x;
    int n0 = blockIdx.x * 64;
    for (int i = tid; i < OUT * OUT; i += 256) ws[i] = W[i];
    if (tid < 64) {
        double mean = g_stats[256 + tid] / (double)Nn;
        double msq  = g_stats[256 + 64 + tid] / (double)Nn;
        double var  = msq - mean * mean;
        float sc = gam[tid] * rsqrtf((float)var + EPS_BN);
        sscale[tid] = sc;
        sshift[tid] = bet[tid] - (float)mean * sc;
    }
    __syncthreads();
    for (int i = tid; i < 64 * OUT; i += 256) {
        int n = i >> 6, k = i & 63;
        int gn = n0 + n;
        float z = 0.f;
        if (gn < Nn) z = fmaxf(sscale[k] * g_y3[(size_t)gn * OUT + k] + sshift[k], 0.f);
        zs[n * 68 + k] = z;
    }
    __syncthreads();
    int ti = tid >> 4, tj = tid & 15;
    float4 acc0 = {0,0,0,0}, acc1 = {0,0,0,0}, acc2 = {0,0,0,0}, acc3 = {0,0,0,0};
    const float4* ws4 = reinterpret_cast<const float4*>(ws);
    #pragma unroll
    for (int k4 = 0; k4 < 16; k4++) {
        float4 z0 = *reinterpret_cast<const float4*>(zs + (4*ti+0)*68 + 4*k4);
        float4 z1 = *reinterpret_cast<const float4*>(zs + (4*ti+1)*68 + 4*k4);
        float4 z2 = *reinterpret_cast<const float4*>(zs + (4*ti+2)*68 + 4*k4);
        float4 z3 = *reinterpret_cast<const float4*>(zs + (4*ti+3)*68 + 4*k4);
        float4 w0 = ws4[(4*k4+0)*16 + tj];
        float4 w1 = ws4[(4*k4+1)*16 + tj];
        float4 w2 = ws4[(4*k4+2)*16 + tj];
        float4 w3 = ws4[(4*k4+3)*16 + tj];
        fma_row(acc0, z0.x, w0); fma_row(acc0, z0.y, w1); fma_row(acc0, z0.z, w2); fma_row(acc0, z0.w, w3);
        fma_row(acc1, z1.x, w0); fma_row(acc1, z1.y, w1); fma_row(acc1, z1.z, w2); fma_row(acc1, z1.w, w3);
        fma_row(acc2, z2.x, w0); fma_row(acc2, z2.y, w1); fma_row(acc2, z2.z, w2); fma_row(acc2, z2.w, w3);
        fma_row(acc3, z3.x, w0); fma_row(acc3, z3.y, w1); fma_row(acc3, z3.z, w2); fma_row(acc3, z3.w, w3);
    }
    float4 bb = *reinterpret_cast<const float4*>(bias + 4*tj);
    float4 accs[4] = {acc0, acc1, acc2, acc3};
    #pragma unroll
    for (int r = 0; r < 4; r++) {
        int gn = n0 + 4*ti + r;
        if (gn < Nn) {
            float4 v = accs[r];
            v.x += bb.x; v.y += bb.y; v.z += bb.z; v.w += bb.w;
            int g = batch[gn];
            red_add_v4(&g_pool[(size_t)g * OUT + 4*tj], v);
            if (tj == 0) atomicAdd(&g_cnt[g], 1.0f);
        }
    }
}

// ---------------- 6: head (per graph) -----------------------------------------
__global__ void head_kernel(const float* __restrict__ action,
                            const float* __restrict__ pinw, const float* __restrict__ pinb,
                            const float* __restrict__ phw,  const float* __restrict__ phb,
                            const float* __restrict__ pow_, const float* __restrict__ pob,
                            float* __restrict__ outp) {
    int g = threadIdx.x;
    if (g >= Bb) return;
    float inv = 1.0f / fmaxf(g_cnt[g], 1.0f);
    float fp[16];
    #pragma unroll
    for (int jj = 0; jj < 16; jj++) {
        float s = 0.f;
        for (int f = 0; f < OUT; f++) s += g_pool[g * OUT + f] * pinw[f * 16 + jj];
        fp[jj] = fmaxf(s * inv + pinb[jj], 0.f);
    }
    float res = pob[0];
    #pragma unroll
    for (int q = 0; q < 10; q++) {
        float s = phb[q];
        #pragma unroll
        for (int jj = 0; jj < 16; jj++) s += fp[jj] * phw[jj * 10 + q];
        #pragma unroll
        for (int a = 0; a < ADIM; a++) s += action[g * ADIM + a] * phw[(16 + a) * 10 + q];
        res += fmaxf(s, 0.f) * pow_[q];
    }
    outp[g] = res;
}

// ---------------- launch -------------------------------------------------------
extern "C" void kernel_launch(void* const* d_in, const int* in_sizes, int n_in,
                              void* d_out, int out_size) {
    const float* x      = (const float*)d_in[0];
    const int*   ei     = (const int*)  d_in[1];
    const float* eattr  = (const float*)d_in[2];
    const int*   batch  = (const int*)  d_in[3];
    const float* action = (const float*)d_in[4];
    const float* node_w = (const float*)d_in[5];
    const float* node_b = (const float*)d_in[6];
    const float* edge_w = (const float*)d_in[7];
    const float* edge_b = (const float*)d_in[8];
    const float* w1 = (const float*)d_in[9];  const float* b1 = (const float*)d_in[10];
    const float* g1 = (const float*)d_in[11]; const float* bb1 = (const float*)d_in[12];
    const float* w2 = (const float*)d_in[13]; const float* b2 = (const float*)d_in[14];
    const float* g2 = (const float*)d_in[15]; const float* bb2 = (const float*)d_in[16];
    const float* w3 = (const float*)d_in[17]; const float* b3 = (const float*)d_in[18];
    const float* g3 = (const float*)d_in[19]; const float* bb3 = (const float*)d_in[20];
    const float* w4 = (const float*)d_in[21]; const float* b4 = (const float*)d_in[22];
    const float* pinw = (const float*)d_in[23]; const float* pinb = (const float*)d_in[24];
    const float* phw  = (const float*)d_in[25]; const float* phb  = (const float*)d_in[26];
    const float* pow_ = (const float*)d_in[27]; const float* pob  = (const float*)d_in[28];

    const int NBLK = (Nn + 63) / 64;  // 1563

    zero_kernel<<<512, 256>>>();
    enc_kernel<<<NBLK, 128>>>(x, node_w, node_b);
    hist_kernel<<<2048, 256>>>(ei);
    scan1_kernel<<<NSCAN, SCAN_B>>>();
    scan2_kernel<<<1, 128>>>();
    scan3_kernel<<<NSCAN, SCAN_B>>>();
    scatter_kernel<<<2048, 256>>>(ei);
    agg_kernel<<<Nn / 8, 256>>>(eattr, edge_w, edge_b);
    stageA_kernel<<<NBLK, 256>>>(w1, b1);
    stageBC_kernel<<<NBLK, 256>>>(w2, b2, g1, bb1, 0);
    stageBC_kernel<<<NBLK, 256>>>(w3, b3, g2, bb2, 1);
    stageD_kernel<<<NBLK, 256>>>(w4, b4, g3, bb3, batch);
    head_kernel<<<1, 64>>>(action, pinw, pinb, phw, phb, pow_, pob, (float*)d_out);
}

// round 9
// speedup vs baseline: 1.0204x; 1.0204x over previous
#include <cuda_runtime.h>
#include <cuda_bf16.h>
#include <cstdint>

#define Nn 100000
#define Ee 3200000
#define Bb 64
#define FIN 64
#define EIN 16
#define ADIM 13
#define Hh 32
#define OUT 64
#define EPS_GEN 1e-7f
#define EPS_BN 1e-5f

#define TR 128                     // rows per block tile in node GEMMs
#define NBLK128 ((Nn + TR - 1) / TR)   // 782

// ---------------- scratch (device globals; no allocs allowed) ----------------
__device__ float  g_h[Nn * Hh];        // node encoder output [N,32]
__device__ float  g_esum[Nn * Hh];     // sum of exp(msg) per dst
__device__ float  g_wsum[Nn * Hh];     // sum of msg*exp(msg) per dst
__device__ float  g_y1[Nn * OUT];
__device__ float  g_y2[Nn * OUT];
__device__ float  g_y3[Nn * OUT];
__device__ double g_stats[3 * 128];    // per stage: [sum(64) | sumsq(64)]
__device__ float  g_pool[Bb * OUT];
__device__ float  g_cnt[Bb];

// ---------------- helpers ----------------
__device__ __forceinline__ void red_add_v4(float* addr, float4 v) {
    asm volatile("red.global.add.v4.f32 [%0], {%1,%2,%3,%4};"
                 :: "l"(addr), "f"(v.x), "f"(v.y), "f"(v.z), "f"(v.w) : "memory");
}

__device__ __forceinline__ void fma_row(float4& acc, float zv, float4 wv) {
    acc.x = fmaf(zv, wv.x, acc.x);
    acc.y = fmaf(zv, wv.y, acc.y);
    acc.z = fmaf(zv, wv.z, acc.z);
    acc.w = fmaf(zv, wv.w, acc.w);
}

// ---------------- 0: zero scratch ----------------
__global__ void zero_kernel() {
    int idx = blockIdx.x * blockDim.x + threadIdx.x;
    int stride = gridDim.x * blockDim.x;
    const int n4 = (Nn * Hh) / 4;
    float4 z4 = make_float4(0.f, 0.f, 0.f, 0.f);
    for (int i = idx; i < n4; i += stride) {
        reinterpret_cast<float4*>(g_esum)[i] = z4;
        reinterpret_cast<float4*>(g_wsum)[i] = z4;
    }
    for (int i = idx; i < Bb * OUT; i += stride) g_pool[i] = 0.f;
    for (int i = idx; i < Bb; i += stride) g_cnt[i] = 0.f;
    for (int i = idx; i < 3 * 128; i += stride) g_stats[i] = 0.0;
}

// ---------------- 1: node encoder  h = x @ node_w + node_b  [N,64]->[N,32] ----
// tile: 128 rows x 32 cols; warp = 32 rows x 16 cols (1 row/thread)
__global__ void __launch_bounds__(256) enc_kernel(const float* __restrict__ x,
                                                  const float* __restrict__ W,
                                                  const float* __restrict__ bias) {
    __shared__ __align__(16) float zs[FIN * (TR + 1)];   // [k][row], stride 129
    __shared__ __align__(16) float ws[FIN * Hh];         // [k][32]
    int tid = threadIdx.x;
    int n0 = blockIdx.x * TR;
    for (int i = tid; i < (FIN * Hh) / 4; i += 256)
        reinterpret_cast<float4*>(ws)[i] = reinterpret_cast<const float4*>(W)[i];
    // loader: 128 rows x 64 k = 2048 float4
    #pragma unroll
    for (int it = 0; it < 8; it++) {
        int idx = tid + it * 256;
        int row = idx >> 4, k4 = idx & 15;
        int gn = n0 + row;
        float4 v = make_float4(0.f, 0.f, 0.f, 0.f);
        if (gn < Nn) v = *reinterpret_cast<const float4*>(x + (size_t)gn * FIN + 4 * k4);
        zs[(4*k4+0) * (TR+1) + row] = v.x;
        zs[(4*k4+1) * (TR+1) + row] = v.y;
        zs[(4*k4+2) * (TR+1) + row] = v.z;
        zs[(4*k4+3) * (TR+1) + row] = v.w;
    }
    __syncthreads();
    int lane = tid & 31, w = tid >> 5;
    int cg = w & 1;           // col group: cols 16*cg .. 16*cg+15
    int rq = w >> 1;          // row quarter
    int rl = 32 * rq + lane;  // local row
    float4 a0 = {0,0,0,0}, a1 = {0,0,0,0}, a2 = {0,0,0,0}, a3 = {0,0,0,0};
    const float4* ws4 = reinterpret_cast<const float4*>(ws);
    #pragma unroll 8
    for (int k = 0; k < FIN; k++) {
        float z = zs[k * (TR+1) + rl];
        const float4* wr = ws4 + k * 8 + cg * 4;
        fma_row(a0, z, wr[0]); fma_row(a1, z, wr[1]);
        fma_row(a2, z, wr[2]); fma_row(a3, z, wr[3]);
    }
    int gn = n0 + rl;
    if (gn < Nn) {
        const float4* b4 = reinterpret_cast<const float4*>(bias) + cg * 4;
        float4 vv;
        float* op = g_h + (size_t)gn * Hh + 16 * cg;
        vv = a0; vv.x += b4[0].x; vv.y += b4[0].y; vv.z += b4[0].z; vv.w += b4[0].w;
        *reinterpret_cast<float4*>(op + 0) = vv;
        vv = a1; vv.x += b4[1].x; vv.y += b4[1].y; vv.z += b4[1].z; vv.w += b4[1].w;
        *reinterpret_cast<float4*>(op + 4) = vv;
        vv = a2; vv.x += b4[2].x; vv.y += b4[2].y; vv.z += b4[2].z; vv.w += b4[2].w;
        *reinterpret_cast<float4*>(op + 8) = vv;
        vv = a3; vv.x += b4[3].x; vv.y += b4[3].y; vv.z += b4[3].z; vv.w += b4[3].w;
        *reinterpret_cast<float4*>(op + 12) = vv;
    }
}

// ---------------- 2: edge pass (msg, exp, atomic segment sums) ----------------
__global__ void __launch_bounds__(256) edge_kernel(const int* __restrict__ ei,
                                                   const float* __restrict__ eattr,
                                                   const float* __restrict__ ew,
                                                   const float* __restrict__ eb) {
    __shared__ __align__(16) float sattr[32 * 20];
    __shared__ __align__(16) float sws[EIN * Hh];   // 16x32
    __shared__ int ssrc[32];
    __shared__ int sdst[32];
    int tid = threadIdx.x;
    for (int i = tid; i < EIN * Hh; i += 256) sws[i] = ew[i];
    int j = tid & 7;          // feature quad (feats 4j..4j+3)
    int el = tid >> 3;        // edge within tile (0..31)
    float4 eb4 = *reinterpret_cast<const float4*>(eb + 4*j);
    const float4* w4p = reinterpret_cast<const float4*>(sws); // [k][8]
    const int ntiles = Ee / 32;
    for (int t = blockIdx.x; t < ntiles; t += gridDim.x) {
        int e0 = t * 32;
        __syncthreads();
        {
            const float2* ap = reinterpret_cast<const float2*>(eattr + (size_t)e0 * EIN);
            float2 v = ap[tid];
            int row = tid >> 3, col = (tid & 7) * 2;
            sattr[row * 20 + col]     = v.x;
            sattr[row * 20 + col + 1] = v.y;
            if (tid < 32) ssrc[tid] = ei[e0 + tid];
            else if (tid < 64) sdst[tid - 32] = ei[Ee + e0 + (tid - 32)];
        }
        __syncthreads();
        int src = ssrc[el], dst = sdst[el];
        float4 ea = eb4;
        const float4* a4p = reinterpret_cast<const float4*>(sattr + el * 20);
        #pragma unroll
        for (int k4 = 0; k4 < 4; k4++) {
            float4 a4 = a4p[k4];
            float4 w0 = w4p[(4*k4+0)*8 + j];
            float4 w1 = w4p[(4*k4+1)*8 + j];
            float4 w2 = w4p[(4*k4+2)*8 + j];
            float4 w3 = w4p[(4*k4+3)*8 + j];
            fma_row(ea, a4.x, w0); fma_row(ea, a4.y, w1); fma_row(ea, a4.z, w2); fma_row(ea, a4.w, w3);
        }
        float4 hv = *reinterpret_cast<const float4*>(g_h + (size_t)src * Hh + 4*j);
        float4 m;
        m.x = fmaxf(hv.x + ea.x, 0.f) + EPS_GEN;
        m.y = fmaxf(hv.y + ea.y, 0.f) + EPS_GEN;
        m.z = fmaxf(hv.z + ea.z, 0.f) + EPS_GEN;
        m.w = fmaxf(hv.w + ea.w, 0.f) + EPS_GEN;
        float4 p;
        p.x = __expf(m.x); p.y = __expf(m.y); p.z = __expf(m.z); p.w = __expf(m.w);
        float* base_e = g_esum + (size_t)dst * Hh + 4*j;
        float* base_w = g_wsum + (size_t)dst * Hh + 4*j;
        red_add_v4(base_e, p);
        red_add_v4(base_w, make_float4(m.x*p.x, m.y*p.y, m.z*p.z, m.w*p.w));
    }
}

// ---------------- node-GEMM consumer (cols=64), shared by stages A/B/C/D ------
// tile: 128 rows x 64 cols; warp = 64 rows x 16 cols (2 rows/thread)
struct StageOut {
    float4 v0[4];   // row r0, 16 cols
    float4 v1[4];   // row r1
    int gn0, gn1;
    int cg, lane;
};

template<int K>
__device__ __forceinline__ void gemm_consume(const float* zs, const float* ws,
                                             const float* bias, StageOut& so,
                                             int n0, int tid) {
    int lane = tid & 31, w = tid >> 5;
    int cg = w & 3;            // cols 16*cg..
    int rh = w >> 2;           // row half
    int rl0 = 64 * rh + lane;  // local rows rl0, rl0+32
    float4 a0[4] = {{0,0,0,0},{0,0,0,0},{0,0,0,0},{0,0,0,0}};
    float4 a1[4] = {{0,0,0,0},{0,0,0,0},{0,0,0,0},{0,0,0,0}};
    const float4* ws4 = reinterpret_cast<const float4*>(ws);
    #pragma unroll 8
    for (int k = 0; k < K; k++) {
        float z0 = zs[k * (TR+1) + rl0];
        float z1 = zs[k * (TR+1) + rl0 + 32];
        const float4* wr = ws4 + k * 16 + cg * 4;
        float4 w0 = wr[0], w1 = wr[1], w2 = wr[2], w3 = wr[3];
        fma_row(a0[0], z0, w0); fma_row(a0[1], z0, w1);
        fma_row(a0[2], z0, w2); fma_row(a0[3], z0, w3);
        fma_row(a1[0], z1, w0); fma_row(a1[1], z1, w1);
        fma_row(a1[2], z1, w2); fma_row(a1[3], z1, w3);
    }
    const float4* b4 = reinterpret_cast<const float4*>(bias) + cg * 4;
    #pragma unroll
    for (int i = 0; i < 4; i++) {
        float4 bb = b4[i];
        a0[i].x += bb.x; a0[i].y += bb.y; a0[i].z += bb.z; a0[i].w += bb.w;
        a1[i].x += bb.x; a1[i].y += bb.y; a1[i].z += bb.z; a1[i].w += bb.w;
        so.v0[i] = a0[i]; so.v1[i] = a1[i];
    }
    so.gn0 = n0 + rl0;
    so.gn1 = n0 + rl0 + 32;
    so.cg = cg; so.lane = lane;
}

__device__ __forceinline__ void store_and_stats(StageOut& so, float* out,
                                                float* ssum, float* ssq) {
    bool ok0 = so.gn0 < Nn, ok1 = so.gn1 < Nn;
    float* op0 = out + (size_t)so.gn0 * OUT + 16 * so.cg;
    float* op1 = out + (size_t)so.gn1 * OUT + 16 * so.cg;
    #pragma unroll
    for (int i = 0; i < 4; i++) {
        if (ok0) *reinterpret_cast<float4*>(op0 + 4*i) = so.v0[i];
        else so.v0[i] = make_float4(0,0,0,0);
        if (ok1) *reinterpret_cast<float4*>(op1 + 4*i) = so.v1[i];
        else so.v1[i] = make_float4(0,0,0,0);
    }
    // rotated shared atomics to reduce contention
    #pragma unroll
    for (int i = 0; i < 4; i++) {
        int q = ((so.lane & 3) + i) & 3;
        float4 s0 = so.v0[q], s1 = so.v1[q];
        int c = 16 * so.cg + 4 * q;
        atomicAdd(&ssum[c+0], s0.x + s1.x);
        atomicAdd(&ssum[c+1], s0.y + s1.y);
        atomicAdd(&ssum[c+2], s0.z + s1.z);
        atomicAdd(&ssum[c+3], s0.w + s1.w);
        atomicAdd(&ssq[c+0], s0.x*s0.x + s1.x*s1.x);
        atomicAdd(&ssq[c+1], s0.y*s0.y + s1.y*s1.y);
        atomicAdd(&ssq[c+2], s0.z*s0.z + s1.z*s1.z);
        atomicAdd(&ssq[c+3], s0.w*s0.w + s1.w*s1.w);
    }
}

// ---------------- 3: stage A  z = agg + h ; y1 = z@W1+b1 ; stats1 -------------
__global__ void __launch_bounds__(256) stageA_kernel(const float* __restrict__ W,
                                                     const float* __restrict__ bias) {
    __shared__ __align__(16) float zs[Hh * (TR + 1)];
    __shared__ __align__(16) float ws[Hh * OUT];
    __shared__ float ssum[64], ssq[64];
    int tid = threadIdx.x;
    int n0 = blockIdx.x * TR;
    for (int i = tid; i < (Hh * OUT) / 4; i += 256)
        reinterpret_cast<float4*>(ws)[i] = reinterpret_cast<const float4*>(W)[i];
    if (tid < 64) { ssum[tid] = 0.f; ssq[tid] = 0.f; }
    // loader: 128 rows x 32 k = 1024 float4
    #pragma unroll
    for (int it = 0; it < 4; it++) {
        int idx = tid + it * 256;
        int row = idx >> 3, k4 = idx & 7;
        int gn = n0 + row;
        float4 z = make_float4(0,0,0,0);
        if (gn < Nn) {
            float4 es = *reinterpret_cast<const float4*>(g_esum + (size_t)gn * Hh + 4*k4);
            float4 wsu = *reinterpret_cast<const float4*>(g_wsum + (size_t)gn * Hh + 4*k4);
            float4 hv = *reinterpret_cast<const float4*>(g_h + (size_t)gn * Hh + 4*k4);
            z.x = ((es.x > 0.f) ? wsu.x / es.x : 0.f) + hv.x;
            z.y = ((es.y > 0.f) ? wsu.y / es.y : 0.f) + hv.y;
            z.z = ((es.z > 0.f) ? wsu.z / es.z : 0.f) + hv.z;
            z.w = ((es.w > 0.f) ? wsu.w / es.w : 0.f) + hv.w;
        }
        zs[(4*k4+0) * (TR+1) + row] = z.x;
        zs[(4*k4+1) * (TR+1) + row] = z.y;
        zs[(4*k4+2) * (TR+1) + row] = z.z;
        zs[(4*k4+3) * (TR+1) + row] = z.w;
    }
    __syncthreads();
    StageOut so;
    gemm_consume<Hh>(zs, ws, bias, so, n0, tid);
    store_and_stats(so, g_y1, ssum, ssq);
    __syncthreads();
    if (tid < 64) {
        atomicAdd(&g_stats[tid],      (double)ssum[tid]);
        atomicAdd(&g_stats[64 + tid], (double)ssq[tid]);
    }
}

// ---------------- 4: stages B/C  z=relu(bn(in)) ; out=z@W+b ; stats ------------
__global__ void __launch_bounds__(256) stageBC_kernel(const float* __restrict__ W,
                                                      const float* __restrict__ bias,
                                                      const float* __restrict__ gam,
                                                      const float* __restrict__ bet,
                                                      int sel) {
    __shared__ __align__(16) float zs[OUT * (TR + 1)];
    __shared__ __align__(16) float ws[OUT * OUT];
    __shared__ float ssum[64], ssq[64], sscale[64], sshift[64];
    const float* in  = sel ? g_y2 : g_y1;
    float*       out = sel ? g_y3 : g_y2;
    int sin  = sel ? 128 : 0;
    int sout = sel ? 256 : 128;
    int tid = threadIdx.x;
    int n0 = blockIdx.x * TR;
    for (int i = tid; i < (OUT * OUT) / 4; i += 256)
        reinterpret_cast<float4*>(ws)[i] = reinterpret_cast<const float4*>(W)[i];
    if (tid < 64) {
        double mean = g_stats[sin + tid] / (double)Nn;
        double msq  = g_stats[sin + 64 + tid] / (double)Nn;
        double var  = msq - mean * mean;
        float sc = gam[tid] * rsqrtf((float)var + EPS_BN);
        sscale[tid] = sc;
        sshift[tid] = bet[tid] - (float)mean * sc;
        ssum[tid] = 0.f; ssq[tid] = 0.f;
    }
    __syncthreads();
    // loader: 128 rows x 64 k = 2048 float4
    #pragma unroll
    for (int it = 0; it < 8; it++) {
        int idx = tid + it * 256;
        int row = idx >> 4, k4 = idx & 15;
        int gn = n0 + row;
        float4 v = make_float4(0,0,0,0);
        if (gn < Nn) v = *reinterpret_cast<const float4*>(in + (size_t)gn * OUT + 4*k4);
        zs[(4*k4+0) * (TR+1) + row] = fmaxf(sscale[4*k4+0] * v.x + sshift[4*k4+0], 0.f);
        zs[(4*k4+1) * (TR+1) + row] = fmaxf(sscale[4*k4+1] * v.y + sshift[4*k4+1], 0.f);
        zs[(4*k4+2) * (TR+1) + row] = fmaxf(sscale[4*k4+2] * v.z + sshift[4*k4+2], 0.f);
        zs[(4*k4+3) * (TR+1) + row] = fmaxf(sscale[4*k4+3] * v.w + sshift[4*k4+3], 0.f);
    }
    __syncthreads();
    StageOut so;
    gemm_consume<OUT>(zs, ws, bias, so, n0, tid);
    store_and_stats(so, out, ssum, ssq);
    __syncthreads();
    if (tid < 64) {
        atomicAdd(&g_stats[sout + tid],      (double)ssum[tid]);
        atomicAdd(&g_stats[sout + 64 + tid], (double)ssq[tid]);
    }
}

// ---------------- 5: stage D  node_out = relu(bn3(y3))@W4+b4, pooled -----------
__global__ void __launch_bounds__(256) stageD_kernel(const float* __restrict__ W,
                                                     const float* __restrict__ bias,
                                                     const float* __restrict__ gam,
                                                     const float* __restrict__ bet,
                                                     const int* __restrict__ batch) {
    __shared__ __align__(16) float zs[OUT * (TR + 1)];
    __shared__ __align__(16) float ws[OUT * OUT];
    __shared__ float sscale[64], sshift[64];
    int tid = threadIdx.x;
    int n0 = blockIdx.x * TR;
    for (int i = tid; i < (OUT * OUT) / 4; i += 256)
        reinterpret_cast<float4*>(ws)[i] = reinterpret_cast<const float4*>(W)[i];
    if (tid < 64) {
        double mean = g_stats[256 + tid] / (double)Nn;
        double msq  = g_stats[256 + 64 + tid] / (double)Nn;
        double var  = msq - mean * mean;
        float sc = gam[tid] * rsqrtf((float)var + EPS_BN);
        sscale[tid] = sc;
        sshift[tid] = bet[tid] - (float)mean * sc;
    }
    __syncthreads();
    #pragma unroll
    for (int it = 0; it < 8; it++) {
        int idx = tid + it * 256;
        int row = idx >> 4, k4 = idx & 15;
        int gn = n0 + row;
        float4 v = make_float4(0,0,0,0);
        if (gn < Nn) v = *reinterpret_cast<const float4*>(g_y3 + (size_t)gn * OUT + 4*k4);
        zs[(4*k4+0) * (TR+1) + row] = fmaxf(sscale[4*k4+0] * v.x + sshift[4*k4+0], 0.f);
        zs[(4*k4+1) * (TR+1) + row] = fmaxf(sscale[4*k4+1] * v.y + sshift[4*k4+1], 0.f);
        zs[(4*k4+2) * (TR+1) + row] = fmaxf(sscale[4*k4+2] * v.z + sshift[4*k4+2], 0.f);
        zs[(4*k4+3) * (TR+1) + row] = fmaxf(sscale[4*k4+3] * v.w + sshift[4*k4+3], 0.f);
    }
    __syncthreads();
    StageOut so;
    gemm_consume<OUT>(zs, ws, bias, so, n0, tid);
    if (so.gn0 < Nn) {
        int g = batch[so.gn0];
        float* pp = g_pool + (size_t)g * OUT + 16 * so.cg;
        #pragma unroll
        for (int i = 0; i < 4; i++) red_add_v4(pp + 4*i, so.v0[i]);
        if (so.cg == 0) atomicAdd(&g_cnt[g], 1.0f);
    }
    if (so.gn1 < Nn) {
        int g = batch[so.gn1];
        float* pp = g_pool + (size_t)g * OUT + 16 * so.cg;
        #pragma unroll
        for (int i = 0; i < 4; i++) red_add_v4(pp + 4*i, so.v1[i]);
        if (so.cg == 0) atomicAdd(&g_cnt[g], 1.0f);
    }
}

// ---------------- 6: head (per graph) -----------------------------------------
__global__ void head_kernel(const float* __restrict__ action,
                            const float* __restrict__ pinw, const float* __restrict__ pinb,
                            const float* __restrict__ phw,  const float* __restrict__ phb,
                            const float* __restrict__ pow_, const float* __restrict__ pob,
                            float* __restrict__ outp) {
    int g = threadIdx.x;
    if (g >= Bb) return;
    float inv = 1.0f / fmaxf(g_cnt[g], 1.0f);
    float fp[16];
    #pragma unroll
    for (int jj = 0; jj < 16; jj++) {
        float s = 0.f;
        for (int f = 0; f < OUT; f++) s += g_pool[g * OUT + f] * pinw[f * 16 + jj];
        fp[jj] = fmaxf(s * inv + pinb[jj], 0.f);
    }
    float res = pob[0];
    #pragma unroll
    for (int q = 0; q < 10; q++) {
        float s = phb[q];
        #pragma unroll
        for (int jj = 0; jj < 16; jj++) s += fp[jj] * phw[jj * 10 + q];
        #pragma unroll
        for (int a = 0; a < ADIM; a++) s += action[g * ADIM + a] * phw[(16 + a) * 10 + q];
        res += fmaxf(s, 0.f) * pow_[q];
    }
    outp[g] = res;
}

// ---------------- launch -------------------------------------------------------
extern "C" void kernel_launch(void* const* d_in, const int* in_sizes, int n_in,
                              void* d_out, int out_size) {
    const float* x      = (const float*)d_in[0];
    const int*   ei     = (const int*)  d_in[1];
    const float* eattr  = (const float*)d_in[2];
    const int*   batch  = (const int*)  d_in[3];
    const float* action = (const float*)d_in[4];
    const float* node_w = (const float*)d_in[5];
    const float* node_b = (const float*)d_in[6];
    const float* edge_w = (const float*)d_in[7];
    const float* edge_b = (const float*)d_in[8];
    const float* w1 = (const float*)d_in[9];  const float* b1 = (const float*)d_in[10];
    const float* g1 = (const float*)d_in[11]; const float* bb1 = (const float*)d_in[12];
    const float* w2 = (const float*)d_in[13]; const float* b2 = (const float*)d_in[14];
    const float* g2 = (const float*)d_in[15]; const float* bb2 = (const float*)d_in[16];
    const float* w3 = (const float*)d_in[17]; const float* b3 = (const float*)d_in[18];
    const float* g3 = (const float*)d_in[19]; const float* bb3 = (const float*)d_in[20];
    const float* w4 = (const float*)d_in[21]; const float* b4 = (const float*)d_in[22];
    const float* pinw = (const float*)d_in[23]; const float* pinb = (const float*)d_in[24];
    const float* phw  = (const float*)d_in[25]; const float* phb  = (const float*)d_in[26];
    const float* pow_ = (const float*)d_in[27]; const float* pob  = (const float*)d_in[28];

    zero_kernel<<<2048, 256>>>();
    enc_kernel<<<NBLK128, 256>>>(x, node_w, node_b);
    edge_kernel<<<2048, 256>>>(ei, eattr, edge_w, edge_b);
    stageA_kernel<<<NBLK128, 256>>>(w1, b1);
    stageBC_kernel<<<NBLK128, 256>>>(w2, b2, g1, bb1, 0);
    stageBC_kernel<<<NBLK128, 256>>>(w3, b3, g2, bb2, 1);
    stageD_kernel<<<NBLK128, 256>>>(w4, b4, g3, bb3, batch);
    head_kernel<<<1, 64>>>(action, pinw, pinb, phw, phb, pow_, pob, (float*)d_out);
}